// round 5
// baseline (speedup 1.0000x reference)
#include <cuda_runtime.h>
#include <cuda_bf16.h>

#define NB 2
#define NC 64
#define NTOK (64*64*64)                  // 262144 tokens per batch
#define NHEADS 4
#define DH 32
#define GRAM_CHUNKS 256
#define TOK_PER_CTA (NTOK / GRAM_CHUNKS) // 1024

// ---------------- static device scratch (no allocations) ----------------
__device__ float g_Gpart[NB][GRAM_CHUNKS][NC * NC]; // 8 MB partial Grams
__device__ float g_G[NB][NC * NC];                  // reduced Gram
__device__ float g_Mt[NB][NC * NC];                 // final M transposed: [c][o]

typedef unsigned long long ull;

__device__ __forceinline__ ull ffma2(ull a, ull b, ull c) {
    ull d;
    asm("fma.rn.f32x2 %0, %1, %2, %3;" : "=l"(d) : "l"(a), "l"(b), "l"(c));
    return d;
}
__device__ __forceinline__ ull pack2(float x, float y) {
    ull d;
    asm("mov.b64 %0, {%1, %2};" : "=l"(d) : "f"(x), "f"(y));
    return d;
}
__device__ __forceinline__ float2 unpack2(ull v) {
    float2 r;
    asm("mov.b64 {%0, %1}, %2;" : "=f"(r.x), "=f"(r.y) : "l"(v));
    return r;
}

// swizzled float-offset of float4-chunk q (=t>>2) in row c of a [64][64] tile
#define SWZ_OFF(c, q) ((c) * 64 + (((q) ^ ((c) >> 2)) << 2))

// ============ Kernel 1: partial Gram  G = sum_n x[:,n] x[:,n]^T ============
// Xs[c][t] with chunk-XOR swizzle. Token-pair FFMA2: both operands are natural
// register pairs from LDS.128 — zero splat MOVs. acc.x/.y = even/odd token sums.
__global__ __launch_bounds__(256) void gram_kernel(const float* __restrict__ x) {
    __shared__ float Xs[64 * 64];       // 16 KB
    const int b = blockIdx.y;
    const int tid = threadIdx.x;
    const int bi = tid >> 4;            // G row chunk (4 rows)
    const int bj = tid & 15;            // G col chunk (4 cols)
    const float* xb = x + (size_t)b * NC * NTOK + (size_t)blockIdx.x * TOK_PER_CTA;

    ull acc[4][4];
#pragma unroll
    for (int i = 0; i < 4; i++)
#pragma unroll
        for (int j = 0; j < 4; j++) acc[i][j] = 0ULL;

    for (int tt = 0; tt < TOK_PER_CTA; tt += 64) {
        __syncthreads();
        // load 64ch x 64tok tile: 1024 float4, 4 per thread, gmem-coalesced
#pragma unroll
        for (int k = 0; k < 4; k++) {
            int lin = tid + k * 256;
            int c = lin >> 4, q = lin & 15;
            float4 v = *(const float4*)&xb[(size_t)c * NTOK + tt + q * 4];
            *(float4*)&Xs[SWZ_OFF(c, q)] = v;
        }
        __syncthreads();
#pragma unroll
        for (int q = 0; q < 16; q++) {
            float4 A[4], B[4];
#pragma unroll
            for (int i = 0; i < 4; i++) {
                A[i] = *(const float4*)&Xs[SWZ_OFF(4 * bi + i, q)];
                B[i] = *(const float4*)&Xs[SWZ_OFF(4 * bj + i, q)];
            }
            ull a01[4], a23[4], b01[4], b23[4];
#pragma unroll
            for (int i = 0; i < 4; i++) {
                a01[i] = pack2(A[i].x, A[i].y);   // natural pairs (no real MOV)
                a23[i] = pack2(A[i].z, A[i].w);
                b01[i] = pack2(B[i].x, B[i].y);
                b23[i] = pack2(B[i].z, B[i].w);
            }
#pragma unroll
            for (int i = 0; i < 4; i++)
#pragma unroll
                for (int j = 0; j < 4; j++)
                    acc[i][j] = ffma2(a01[i], b01[j],
                                ffma2(a23[i], b23[j], acc[i][j]));
        }
    }
    float* dst = g_Gpart[b][blockIdx.x];
#pragma unroll
    for (int i = 0; i < 4; i++)
#pragma unroll
        for (int j = 0; j < 4; j++) {
            float2 f = unpack2(acc[i][j]);
            dst[(4 * bi + i) * 64 + 4 * bj + j] = f.x + f.y;
        }
}

// ============ Kernel 2: deterministic reduce of Gram partials ============
__global__ void reduce_g() {
    int idx = blockIdx.x * blockDim.x + threadIdx.x;   // 8192 threads
    int b = idx >> 12, e = idx & 4095;
    float s0 = 0.f, s1 = 0.f, s2 = 0.f, s3 = 0.f;
#pragma unroll 8
    for (int k = 0; k < GRAM_CHUNKS; k += 4) {
        s0 += g_Gpart[b][k + 0][e];
        s1 += g_Gpart[b][k + 1][e];
        s2 += g_Gpart[b][k + 2][e];
        s3 += g_Gpart[b][k + 3][e];
    }
    g_G[b][e] = (s0 + s1) + (s2 + s3);
}

// ==== Kernel 3: fused combine + head-reduce. One CTA per batch. ====
// M[b] = sum_h Wout_h (scale * (Wk_h G Wv_h^T / 4096)^T Wq_h); stored [c][o].
// smem: T1 and Am alias (T1 dead after phase 2). Total 45.3 KB < 48 KB.
__global__ __launch_bounds__(256) void combine_kernel(const float* __restrict__ w_qkv,
                                                      const float* __restrict__ w_out) {
    __shared__ float Gs[64 * 65];      // padded G
    __shared__ float T1Am[64 * 32];    // phase1-2: T1[c1][e]; phase3-4: Am[e][c]
    __shared__ float CT[32 * 32];      // ctx[d][e]
    __shared__ float Mac[4096];        // accumulated M^T [c][o]

    const int b = blockIdx.x;
    const int tid = threadIdx.x;
    float* T1 = T1Am;
    float* Am = T1Am;

    for (int i = tid; i < 4096; i += 256) {
        Mac[i] = 0.f;
        Gs[(i >> 6) * 65 + (i & 63)] = g_G[b][i];
    }

    for (int h = 0; h < NHEADS; h++) {
        const float* Wq = w_qkv + (h * DH) * 64;          // [d][c]
        const float* Wk = w_qkv + (128 + h * DH) * 64;    // [d][c]
        const float* Wv = w_qkv + (256 + h * DH) * 64;    // [e][c]
        __syncthreads();

        // Phase 1: T1[c1][e] = sum_c2 G[c1][c2] * Wv[e][c2]
        {
            int base = tid * 8;
            int c1 = base >> 5, e0 = base & 31;
            float a[8] = {0, 0, 0, 0, 0, 0, 0, 0};
            for (int c2 = 0; c2 < 64; c2++) {
                float gv = Gs[c1 * 65 + c2];
#pragma unroll
                for (int r = 0; r < 8; r++) a[r] += gv * __ldg(&Wv[(e0 + r) * 64 + c2]);
            }
#pragma unroll
            for (int r = 0; r < 8; r++) T1[c1 * 32 + e0 + r] = a[r];
        }
        __syncthreads();

        // Phase 2: CT[d][e] = (1/4096) * sum_c1 Wk[d][c1] * T1[c1][e]
        {
            int base = tid * 4;
            int d = base >> 5, e0 = base & 31;
            float a[4] = {0, 0, 0, 0};
            for (int c1 = 0; c1 < 64; c1++) {
                float wk = __ldg(&Wk[d * 64 + c1]);
#pragma unroll
                for (int r = 0; r < 4; r++) a[r] += wk * T1[c1 * 32 + e0 + r];
            }
#pragma unroll
            for (int r = 0; r < 4; r++) CT[d * 32 + e0 + r] = a[r] * (1.0f / 4096.0f);
        }
        __syncthreads();   // T1 reads done — safe to overwrite as Am

        // Phase 3: Am[e][c] = scale * sum_d CT[d][e] * Wq[d][c]
        {
            int base = tid * 8;
            int e = base >> 6, c0 = base & 63;
            float a[8] = {0, 0, 0, 0, 0, 0, 0, 0};
            for (int d = 0; d < 32; d++) {
                float cv = CT[d * 32 + e];
#pragma unroll
                for (int r = 0; r < 8; r++) a[r] += cv * __ldg(&Wq[d * 64 + c0 + r]);
            }
            const float scale = 0.17677669529663687f;   // 32^-0.5
#pragma unroll
            for (int r = 0; r < 8; r++) Am[e * 64 + c0 + r] = a[r] * scale;
        }
        __syncthreads();

        // Phase 4: Mac[c][o] += sum_e Wout[o][h*32+e] * Am[e][c]
        {
            int o = tid >> 2, c0 = (tid & 3) * 16;
            float a[16];
#pragma unroll
            for (int r = 0; r < 16; r++) a[r] = 0.f;
            for (int e = 0; e < 32; e++) {
                float wo = __ldg(&w_out[o * 128 + h * DH + e]);
#pragma unroll
                for (int r = 0; r < 16; r++) a[r] += wo * Am[e * 64 + c0 + r];
            }
#pragma unroll
            for (int r = 0; r < 16; r++) Mac[(c0 + r) * 64 + o] += a[r];
        }
        __syncthreads();   // Am reads done before next head overwrites T1
    }
    for (int i = tid; i < 4096; i += 256) g_Mt[b][i] = Mac[i];
}

// ======== Kernel 4: y = M x + b_out, then channel LayerNorm ========
// CTA = 64ch x 256 tokens, processed as 4 sequential 64-token sub-tiles.
// pool aliases Xs (GEMM input, swizzled [c][t], 4096 fl) and Ys ([t][o] s66,
// 4224 fl) — accumulators are in registers across the sync. Total 36.4 KB.
__global__ __launch_bounds__(256) void apply_kernel(const float* __restrict__ x,
                                                    const float* __restrict__ b_out,
                                                    const float* __restrict__ gain,
                                                    float* __restrict__ out) {
    __shared__ float Ms[4096];      // [c][o] (M transposed)
    __shared__ float pool[64 * 66]; // Xs (GEMM) / Ys (epilogue)
    __shared__ float redS[256], redSS[256];
    __shared__ float stat_mu[64], stat_rs[64];
    __shared__ float bS[64], gS[64];

    const int b = blockIdx.y;
    const int tid = threadIdx.x;
    const int bi = tid >> 4;       // output-channel chunk (4)
    const int bj = tid & 15;       // token chunk (4)

#pragma unroll
    for (int k = 0; k < 16; k++) Ms[tid + k * 256] = g_Mt[b][tid + k * 256];
    if (tid < 64) { bS[tid] = b_out[tid]; gS[tid] = gain[tid]; }

    for (int sub = 0; sub < 4; sub++) {
        const size_t tbase = (size_t)blockIdx.x * 256 + sub * 64;
        const float* xb = x + (size_t)b * NC * NTOK + tbase;
        __syncthreads();   // Ms ready (sub 0) / prev epilogue reads done (sub>0)
#pragma unroll
        for (int k = 0; k < 4; k++) {
            int lin = tid + k * 256;
            int c = lin >> 4, q = lin & 15;
            float4 v = *(const float4*)&xb[(size_t)c * NTOK + q * 4];
            *(float4*)&pool[SWZ_OFF(c, q)] = v;
        }
        __syncthreads();

        ull acc[4][2];
#pragma unroll
        for (int i = 0; i < 4; i++) { acc[i][0] = 0ULL; acc[i][1] = 0ULL; }

#pragma unroll
        for (int c = 0; c < 64; c++) {
            float4 mv = *(const float4*)&Ms[c * 64 + 4 * bi];          // broadcast
            float4 xv = *(const float4*)&pool[SWZ_OFF(c, bj)];         // 4 tokens
            ull xpa = pack2(xv.x, xv.y);   // natural pairs
            ull xpb = pack2(xv.z, xv.w);
            ull m0 = pack2(mv.x, mv.x);    // 4 genuine splats
            ull m1 = pack2(mv.y, mv.y);
            ull m2 = pack2(mv.z, mv.z);
            ull m3 = pack2(mv.w, mv.w);
            acc[0][0] = ffma2(m0, xpa, acc[0][0]);
            acc[0][1] = ffma2(m0, xpb, acc[0][1]);
            acc[1][0] = ffma2(m1, xpa, acc[1][0]);
            acc[1][1] = ffma2(m1, xpb, acc[1][1]);
            acc[2][0] = ffma2(m2, xpa, acc[2][0]);
            acc[2][1] = ffma2(m2, xpb, acc[2][1]);
            acc[3][0] = ffma2(m3, xpa, acc[3][0]);
            acc[3][1] = ffma2(m3, xpb, acc[3][1]);
        }
        __syncthreads();   // all Xs reads complete — reuse pool as Ys

        // Ys[t][o] = y + bias   (stride 66)
#pragma unroll
        for (int i = 0; i < 4; i++) {
            int o = 4 * bi + i;
            float bo = bS[o];
#pragma unroll
            for (int jp = 0; jp < 2; jp++) {
                float2 f = unpack2(acc[i][jp]);
                int t0 = 4 * bj + 2 * jp;
                pool[t0 * 66 + o] = f.x + bo;
                pool[(t0 + 1) * 66 + o] = f.y + bo;
            }
        }
        __syncthreads();

        // per-token mean/var: 4 threads per token, 16 channels each
        {
            int t = tid >> 2, qq = tid & 3;
            float s = 0.f, ss = 0.f;
#pragma unroll
            for (int k = 0; k < 16; k++) {
                float v = pool[t * 66 + 16 * qq + k];
                s += v; ss += v * v;
            }
            redS[tid] = s; redSS[tid] = ss;
        }
        __syncthreads();
        if (tid < 64) {
            float S  = (redS[tid * 4] + redS[tid * 4 + 1]) + (redS[tid * 4 + 2] + redS[tid * 4 + 3]);
            float SS = (redSS[tid * 4] + redSS[tid * 4 + 1]) + (redSS[tid * 4 + 2] + redSS[tid * 4 + 3]);
            float mu = S * (1.0f / 64.0f);
            float var = SS * (1.0f / 64.0f) - mu * mu;
            stat_mu[tid] = mu;
            stat_rs[tid] = rsqrtf(var + 1e-5f);
        }
        __syncthreads();

        // normalize + gain, coalesced store
        float* ob = out + (size_t)b * NC * NTOK + tbase;
#pragma unroll
        for (int k = 0; k < 16; k++) {
            int idx = tid + k * 256;
            int c = idx >> 6, t = idx & 63;
            float v = (pool[t * 66 + c] - stat_mu[t]) * stat_rs[t] * gS[c];
            ob[(size_t)c * NTOK + t] = v;
        }
    }
}

extern "C" void kernel_launch(void* const* d_in, const int* in_sizes, int n_in,
                              void* d_out, int out_size) {
    const float* x     = (const float*)d_in[0];   // [2,64,64,64,64]
    const float* w_qkv = (const float*)d_in[1];   // [384,64]
    const float* w_out = (const float*)d_in[2];   // [64,128]
    const float* b_out = (const float*)d_in[3];   // [64]
    const float* g     = (const float*)d_in[4];   // [64]
    float* out = (float*)d_out;

    gram_kernel<<<dim3(GRAM_CHUNKS, NB), 256>>>(x);
    reduce_g<<<32, 256>>>();
    combine_kernel<<<NB, 256>>>(w_qkv, w_out);
    apply_kernel<<<dim3(NTOK / 256, NB), 256>>>(x, b_out, g, out);
}